// round 6
// baseline (speedup 1.0000x reference)
#include <cuda_runtime.h>
#include <cstdint>

#define VOCAB 50257
#define DIM   2048
#define RNK   64
#define MT    32             // tokens per CTA
#define NDC   128            // d-columns per chunk
#define NCHUNK (DIM / NDC)   // 16
#define NTHREADS 256

// B pre-transposed into mma fragment layout, per 128-col chunk (512 KB)
__device__ float g_Bfrag[DIM * RNK];

__device__ __forceinline__ uint32_t to_tf32(float v) {
    uint32_t r;
    asm("cvt.rna.tf32.f32 %0, %1;" : "=r"(r) : "f"(v));
    return r;
}
__device__ __forceinline__ void mma_tf32(float* d, const float4& a, const float2& b) {
    asm volatile(
        "mma.sync.aligned.m16n8k8.row.col.f32.tf32.tf32.f32 "
        "{%0,%1,%2,%3}, {%4,%5,%6,%7}, {%8,%9}, {%0,%1,%2,%3};"
        : "+f"(d[0]), "+f"(d[1]), "+f"(d[2]), "+f"(d[3])
        : "r"(__float_as_uint(a.x)), "r"(__float_as_uint(a.y)),
          "r"(__float_as_uint(a.z)), "r"(__float_as_uint(a.w)),
          "r"(__float_as_uint(b.x)), "r"(__float_as_uint(b.y)));
}

// ---- prep: Bm[d][r] (f32) -> tf32 fragment layout, per 128-d chunk ----
// frag slot for (n = d&127, r): s=r>>3, kq=r&7, nt=n>>3, n8=n&7
//   lane = n8*4 + (kq&3), reg = kq>>2
//   idx  = chunk*8192 + ((s*16+nt)*32 + lane)*2 + reg
__global__ void prep_B(const float* __restrict__ Bm) {
    int idx = blockIdx.x * blockDim.x + threadIdx.x;   // 0..131071
    int d = idx >> 6, r = idx & 63;
    uint32_t tv = to_tf32(Bm[idx]);
    int chunk = d >> 7, n = d & 127;
    int s = r >> 3, kq = r & 7;
    int nt = n >> 3, n8 = n & 7;
    int lane = n8 * 4 + (kq & 3), reg = kq >> 2;
    g_Bfrag[chunk * 8192 + ((s * 16 + nt) * 32 + lane) * 2 + reg] = __uint_as_float(tv);
}

// ---- main kernel: one CTA per 32-token tile (512 CTAs), loops over 16 d-chunks ----
__global__ void __launch_bounds__(NTHREADS)
lora_main(const int* __restrict__ x,
          const float* __restrict__ W,
          const float* __restrict__ A,
          float* __restrict__ out) {
    __shared__ float As[MT * RNK];     // 8 KB: A fragments
    __shared__ int toks[MT];

    const int tid   = threadIdx.x;
    const int tBase = blockIdx.x * MT;

    if (tid < MT) toks[tid] = x[tBase + tid];
    __syncthreads();   // toks visible to gather

    // ---- gather A into fragment layout ----
    // (t, r): s=r>>3, kq=r&7, mgrp=t>>4 (0..1), row16=t&15, grp=row16&7, hi=row16>>3
    //   lane = grp*4 + (kq&3), reg = (kq>>2)*2 + hi
    //   As[((s*2 + mgrp)*32 + lane)*4 + reg]
    #pragma unroll 4
    for (int i = tid; i < MT * RNK; i += NTHREADS) {
        int t = i & (MT - 1);
        int r = i >> 5;
        uint32_t tv = to_tf32(__ldg(A + (size_t)r * VOCAB + toks[t]));
        int s = r >> 3, kq = r & 7;
        int mgrp = t >> 4, row16 = t & 15;
        int grp = row16 & 7, hi = row16 >> 3;
        int lane = grp * 4 + (kq & 3);
        int reg = (kq >> 2) * 2 + hi;
        As[((s * 2 + mgrp) * 32 + lane) * 4 + reg] = __uint_as_float(tv);
    }
    __syncthreads();   // A frags ready; NO MORE SYNCS — warps run free

    const int wid  = tid >> 5;
    const int lane = tid & 31;
    const int mg   = wid >> 2;        // 0..1 : 16-token half
    const int ng   = wid & 3;         // 0..3 : 32-col quarter
    const int grp  = lane >> 2;
    const int tig  = lane & 3;

    const int row0 = mg * 16 + grp;
    const int tok0 = toks[row0];
    const int tok1 = toks[row0 + 8];

    // this thread's a-fragment pointers (fixed across chunks)
    float4 afrag[8];
    #pragma unroll
    for (int s = 0; s < 8; ++s)
        afrag[s] = *(const float4*)&As[((s * 2 + mg) * 32 + lane) * 4];

    #pragma unroll 1
    for (int c = 0; c < NCHUNK; ++c) {
        const float* bp = g_Bfrag + c * 8192 + (ng * 4 * 32 + lane) * 2;

        float acc[4][4];
        #pragma unroll
        for (int nt = 0; nt < 4; ++nt)
            #pragma unroll
            for (int k = 0; k < 4; ++k) acc[nt][k] = 0.f;

        #pragma unroll
        for (int s = 0; s < 8; ++s) {
            float2 b[4];
            #pragma unroll
            for (int nt = 0; nt < 4; ++nt)
                b[nt] = *(const float2*)(bp + (s * 16 + nt) * 64);
            #pragma unroll
            for (int nt = 0; nt < 4; ++nt)
                mma_tf32(acc[nt], afrag[s], b[nt]);
        }

        // ---- fused epilogue: W gather + 16*lora + coalesced float2 stores ----
        const int col0 = c * NDC + ng * 32 + 2 * tig;
        const float* w0 = W + (size_t)tok0 * DIM + col0;
        const float* w1 = W + (size_t)tok1 * DIM + col0;
        float* o0 = out + (size_t)(tBase + row0) * DIM + col0;
        float* o1 = o0 + (size_t)8 * DIM;
        float2 wv0[4], wv1[4];
        #pragma unroll
        for (int nt = 0; nt < 4; ++nt) {
            wv0[nt] = __ldg((const float2*)(w0 + nt * 8));
            wv1[nt] = __ldg((const float2*)(w1 + nt * 8));
        }
        #pragma unroll
        for (int nt = 0; nt < 4; ++nt) {
            float2 r0, r1;
            r0.x = fmaf(16.f, acc[nt][0], wv0[nt].x);
            r0.y = fmaf(16.f, acc[nt][1], wv0[nt].y);
            r1.x = fmaf(16.f, acc[nt][2], wv1[nt].x);
            r1.y = fmaf(16.f, acc[nt][3], wv1[nt].y);
            *(float2*)(o0 + nt * 8) = r0;
            *(float2*)(o1 + nt * 8) = r1;
        }
    }
}

extern "C" void kernel_launch(void* const* d_in, const int* in_sizes, int n_in,
                              void* d_out, int out_size) {
    const int*   x  = (const int*)d_in[0];
    const float* W  = (const float*)d_in[1];
    const float* A  = (const float*)d_in[2];
    const float* Bm = (const float*)d_in[3];
    float* out = (float*)d_out;

    const int ntok = in_sizes[0];   // 16384

    prep_B<<<(DIM * RNK) / NTHREADS, NTHREADS>>>(Bm);
    lora_main<<<ntok / MT, NTHREADS>>>(x, W, A, out);
}

// round 8
// speedup vs baseline: 1.7315x; 1.7315x over previous
#include <cuda_runtime.h>
#include <cstdint>

#define VOCAB 50257
#define DIM   2048
#define RNK   64
#define MT    64             // tokens per CTA
#define NDC   128            // d-columns per chunk
#define NCHUNK (DIM / NDC)   // 16
#define NTHREADS 256

// B pre-transposed into mma fragment layout, per 128-col chunk (512 KB)
__device__ float g_Bfrag[DIM * RNK];

__device__ __forceinline__ uint32_t smem_u32(const void* p) {
    uint32_t a;
    asm("{ .reg .u64 t; cvta.to.shared.u64 t, %1; cvt.u32.u64 %0, t; }" : "=r"(a) : "l"(p));
    return a;
}
__device__ __forceinline__ uint32_t to_tf32(float v) {
    uint32_t r;
    asm("cvt.rna.tf32.f32 %0, %1;" : "=r"(r) : "f"(v));
    return r;
}
__device__ __forceinline__ void cpa16(uint32_t dst, const void* src) {
    asm volatile("cp.async.cg.shared.global [%0], [%1], 16;" :: "r"(dst), "l"(src));
}
__device__ __forceinline__ void mma_tf32(float* d, const float4& a, const float2& b) {
    asm volatile(
        "mma.sync.aligned.m16n8k8.row.col.f32.tf32.tf32.f32 "
        "{%0,%1,%2,%3}, {%4,%5,%6,%7}, {%8,%9}, {%0,%1,%2,%3};"
        : "+f"(d[0]), "+f"(d[1]), "+f"(d[2]), "+f"(d[3])
        : "r"(__float_as_uint(a.x)), "r"(__float_as_uint(a.y)),
          "r"(__float_as_uint(a.z)), "r"(__float_as_uint(a.w)),
          "r"(__float_as_uint(b.x)), "r"(__float_as_uint(b.y)));
}

// ---- prep: Bm[d][r] (f32) -> tf32 fragment layout, per 128-d chunk ----
// frag slot for (n = d&127, r): s=r>>3, kq=r&7, nt=n>>3, n8=n&7
//   lane = n8*4 + (kq&3), reg = kq>>2
//   idx  = chunk*8192 + ((s*16+nt)*32 + lane)*2 + reg
__global__ void prep_B(const float* __restrict__ Bm) {
    int idx = blockIdx.x * blockDim.x + threadIdx.x;   // 0..131071
    int d = idx >> 6, r = idx & 63;
    uint32_t tv = to_tf32(Bm[idx]);
    int chunk = d >> 7, n = d & 127;
    int s = r >> 3, kq = r & 7;
    int nt = n >> 3, n8 = n & 7;
    int lane = n8 * 4 + (kq & 3), reg = kq >> 2;
    g_Bfrag[chunk * 8192 + ((s * 16 + nt) * 32 + lane) * 2 + reg] = __uint_as_float(tv);
}

// ---- main kernel: one CTA per 64-token tile (256 CTAs), 16 d-chunks ----
__global__ void __launch_bounds__(NTHREADS, 2)
lora_main(const int* __restrict__ x,
          const float* __restrict__ W,
          const float* __restrict__ A,
          float* __restrict__ out) {
    extern __shared__ float sm[];
    float* As   = sm;             // 4096 floats: A fragments (16 KB)
    float* Bbuf = sm + 4096;      // 2 x 8192 floats: B ping-pong (64 KB)
    int*   toks = (int*)(sm + 4096 + 16384);

    const int tid   = threadIdx.x;
    const int tBase = blockIdx.x * MT;

    if (tid < MT) toks[tid] = x[tBase + tid];

    // prefetch B chunk 0
    {
        uint32_t dst = smem_u32(Bbuf);
        #pragma unroll
        for (int j = 0; j < 8; ++j) {
            int i4 = j * NTHREADS + tid;
            cpa16(dst + i4 * 16, g_Bfrag + i4 * 4);
        }
        asm volatile("cp.async.commit_group;");
    }
    __syncthreads();   // toks visible

    // ---- gather A into fragment layout ----
    // (t, r): s=r>>3, kq=r&7, mtile=t>>4 (0..3), row16=t&15, grp=row16&7, hi=row16>>3
    //   lane = grp*4 + (kq&3), reg = (kq>>2)*2 + hi
    //   As[((s*4 + mtile)*32 + lane)*4 + reg]
    #pragma unroll 4
    for (int i = tid; i < MT * RNK; i += NTHREADS) {
        int t = i & (MT - 1);
        int r = i >> 6;
        uint32_t tv = to_tf32(__ldg(A + (size_t)r * VOCAB + toks[t]));
        int s = r >> 3, kq = r & 7;
        int mtile = t >> 4, row16 = t & 15;
        int grp = row16 & 7, hi = row16 >> 3;
        int lane = grp * 4 + (kq & 3);
        int reg = (kq >> 2) * 2 + hi;
        As[((s * 4 + mtile) * 32 + lane) * 4 + reg] = __uint_as_float(tv);
    }

    const int wid  = tid >> 5;
    const int lane = tid & 31;
    const int mg   = wid >> 2;        // 0..1 : 32-token half
    const int ng   = wid & 3;         // 0..3 : 32-col quarter
    const int grp  = lane >> 2;
    const int tig  = lane & 3;

    // token ids for this thread's 4 output rows (stable across chunks)
    int tok[2][2], rowg[2];
    #pragma unroll
    for (int mt = 0; mt < 2; ++mt) {
        int r0 = mg * 32 + mt * 16 + grp;
        rowg[mt] = r0;
        tok[mt][0] = toks[r0];        // toks valid (written before __syncthreads)
        tok[mt][1] = toks[r0 + 8];
    }

    #pragma unroll 1
    for (int c = 0; c < NCHUNK; ++c) {
        float* curB = Bbuf + (c & 1) * 8192;
        if (c + 1 < NCHUNK) {
            const float* src = g_Bfrag + (c + 1) * 8192;
            uint32_t dst = smem_u32(Bbuf + ((c + 1) & 1) * 8192);
            #pragma unroll
            for (int j = 0; j < 8; ++j) {
                int i4 = j * NTHREADS + tid;
                cpa16(dst + i4 * 16, src + i4 * 4);
            }
            asm volatile("cp.async.commit_group;");
            asm volatile("cp.async.wait_group 1;");
        } else {
            asm volatile("cp.async.wait_group 0;");
        }
        __syncthreads();   // B[cur] ready; A frags ready (c==0)

        // ---- MMA: warp tile m32 x n32, K=64 ----
        float acc[2][4][4];
        #pragma unroll
        for (int mt = 0; mt < 2; ++mt)
            #pragma unroll
            for (int nt = 0; nt < 4; ++nt)
                #pragma unroll
                for (int k = 0; k < 4; ++k) acc[mt][nt][k] = 0.f;

        #pragma unroll
        for (int s = 0; s < 8; ++s) {
            float4 a[2];
            float2 b[4];
            #pragma unroll
            for (int mt = 0; mt < 2; ++mt)
                a[mt] = *(const float4*)&As[((s * 4 + mg * 2 + mt) * 32 + lane) * 4];
            #pragma unroll
            for (int nt = 0; nt < 4; ++nt)
                b[nt] = *(const float2*)&curB[((s * 16 + ng * 4 + nt) * 32 + lane) * 2];
            #pragma unroll
            for (int mt = 0; mt < 2; ++mt)
                #pragma unroll
                for (int nt = 0; nt < 4; ++nt)
                    mma_tf32(acc[mt][nt], a[mt], b[nt]);
        }
        __syncthreads();   // mma LDS done before next prefetch overwrites

        // ---- fused epilogue: W gather + 16*lora + coalesced float2 stores ----
        const int col0 = c * NDC + ng * 32 + 2 * tig;
        #pragma unroll
        for (int mt = 0; mt < 2; ++mt) {
            const float* w0 = W + (size_t)tok[mt][0] * DIM + col0;
            const float* w1 = W + (size_t)tok[mt][1] * DIM + col0;
            float* o0 = out + (size_t)(tBase + rowg[mt]) * DIM + col0;
            float* o1 = o0 + (size_t)8 * DIM;
            float2 wv0[4], wv1[4];
            #pragma unroll
            for (int nt = 0; nt < 4; ++nt) {
                wv0[nt] = __ldg((const float2*)(w0 + nt * 8));
                wv1[nt] = __ldg((const float2*)(w1 + nt * 8));
            }
            #pragma unroll
            for (int nt = 0; nt < 4; ++nt) {
                float2 r0, r1;
                r0.x = fmaf(16.f, acc[mt][nt][0], wv0[nt].x);
                r0.y = fmaf(16.f, acc[mt][nt][1], wv0[nt].y);
                r1.x = fmaf(16.f, acc[mt][nt][2], wv1[nt].x);
                r1.y = fmaf(16.f, acc[mt][nt][3], wv1[nt].y);
                *(float2*)(o0 + nt * 8) = r0;
                *(float2*)(o1 + nt * 8) = r1;
            }
        }
    }
}

extern "C" void kernel_launch(void* const* d_in, const int* in_sizes, int n_in,
                              void* d_out, int out_size) {
    const int*   x  = (const int*)d_in[0];
    const float* W  = (const float*)d_in[1];
    const float* A  = (const float*)d_in[2];
    const float* Bm = (const float*)d_in[3];
    float* out = (float*)d_out;

    const int ntok = in_sizes[0];   // 16384

    const int smemBytes = (4096 + 16384) * 4 + MT * 4;   // 82,176 B
    cudaFuncSetAttribute(lora_main,
                         cudaFuncAttributeMaxDynamicSharedMemorySize, smemBytes);

    prep_B<<<(DIM * RNK) / NTHREADS, NTHREADS>>>(Bm);
    lora_main<<<ntok / MT, NTHREADS, smemBytes>>>(x, W, A, out);
}